// round 1
// baseline (speedup 1.0000x reference)
#include <cuda_runtime.h>
#include <cuda_bf16.h>
#include <cstdint>
#include <cstddef>

// ---------------------------------------------------------------------------
// Problem constants (MambaBlock): d_model=1024, d_inner=2048, d_conv=4,
// d_state=16, dt_rank=64, B=2, L=2048
// ---------------------------------------------------------------------------
#define BSZ     2
#define LSEQ    2048
#define DMODEL  1024
#define DINNER  2048
#define DCONV   4
#define DSTATE  16
#define DTRANK  64
#define NTOK    (BSZ * LSEQ)          // 4096 tokens
#define XDBL_W  (DTRANK + 2 * DSTATE) // 96

// ---------------------------------------------------------------------------
// Scratch: __device__ globals (no cudaMalloc allowed). ~162 MB total (bss).
// ---------------------------------------------------------------------------
__device__ float g_xr   [(size_t)NTOK * (2 * DINNER)]; // in_proj out: [xi | res]
__device__ float g_xc   [(size_t)NTOK * DINNER];       // conv+silu out (u)
__device__ float g_xdbl [(size_t)NTOK * XDBL_W];       // [dt(64) | B(16) | C(16)]
__device__ float g_delta[(size_t)NTOK * DINNER];       // softplus(dt @ W + b)
__device__ float g_y    [(size_t)NTOK * DINNER];       // gated scan output

// ---------------------------------------------------------------------------
// Helpers
// ---------------------------------------------------------------------------
__device__ __forceinline__ float softplusf(float x) {
    // log(1 + exp(x)), overflow-safe
    return fmaxf(x, 0.0f) + log1pf(__expf(-fabsf(x)));
}
__device__ __forceinline__ float siluf(float x) {
    return x * (1.0f / (1.0f + __expf(-x)));
}

// ---------------------------------------------------------------------------
// SGEMM: C[M,N] = A[M,K] @ B[K,N], all row-major, fp32.
// 128x128 block, BK=8, 256 threads, 8x8 per-thread tile.
// EPI==1: C = softplus(acc + bias[col])   (for the dt_proj GEMM)
// Requires: M%128==0, K%8==0, lda/ldb/ldc %4==0, N%4==0.
// ---------------------------------------------------------------------------
template <int EPI>
__global__ __launch_bounds__(256) void sgemm128(
    const float* __restrict__ A, const float* __restrict__ B,
    float* __restrict__ C, const float* __restrict__ bias,
    int M, int N, int K, int lda, int ldb, int ldc)
{
    __shared__ float As[8][128];   // transposed A tile
    __shared__ float Bs[8][128];

    const int tid  = threadIdx.x;
    const int row0 = blockIdx.y * 128;
    const int col0 = blockIdx.x * 128;

    const int arow = tid >> 1;            // 0..127
    const int acol = (tid & 1) * 4;       // 0 or 4
    const int brow = tid >> 5;            // 0..7
    const int bcol = (tid & 31) * 4;      // 0..124
    const int trow = (tid >> 4) * 8;      // 0..120
    const int tcol = (tid & 15) * 8;      // 0..120

    float acc[8][8];
    #pragma unroll
    for (int i = 0; i < 8; i++)
        #pragma unroll
        for (int j = 0; j < 8; j++) acc[i][j] = 0.0f;

    const float* Ap = A + (size_t)(row0 + arow) * lda + acol;
    const float* Bp = B + (size_t)brow * ldb + col0 + bcol;
    const bool bok = (col0 + bcol) < N;   // N%4==0 -> vector fully in/out

    for (int k0 = 0; k0 < K; k0 += 8) {
        float4 av = *(const float4*)(Ap + k0);
        As[acol + 0][arow] = av.x;
        As[acol + 1][arow] = av.y;
        As[acol + 2][arow] = av.z;
        As[acol + 3][arow] = av.w;
        float4 bv = make_float4(0.f, 0.f, 0.f, 0.f);
        if (bok) bv = *(const float4*)(Bp + (size_t)k0 * ldb);
        *(float4*)&Bs[brow][bcol] = bv;
        __syncthreads();

        #pragma unroll
        for (int k = 0; k < 8; k++) {
            float ra[8], rb[8];
            *(float4*)&ra[0] = *(const float4*)&As[k][trow];
            *(float4*)&ra[4] = *(const float4*)&As[k][trow + 4];
            *(float4*)&rb[0] = *(const float4*)&Bs[k][tcol];
            *(float4*)&rb[4] = *(const float4*)&Bs[k][tcol + 4];
            #pragma unroll
            for (int i = 0; i < 8; i++)
                #pragma unroll
                for (int j = 0; j < 8; j++)
                    acc[i][j] = fmaf(ra[i], rb[j], acc[i][j]);
        }
        __syncthreads();
    }

    float bb[8];
    if (EPI == 1) {
        #pragma unroll
        for (int j = 0; j < 8; j++) bb[j] = bias[col0 + tcol + j];
    }

    #pragma unroll
    for (int i = 0; i < 8; i++) {
        size_t r = (size_t)(row0 + trow + i);
        #pragma unroll
        for (int j = 0; j < 8; j += 4) {
            int c = col0 + tcol + j;
            if (c < N) {
                float v0 = acc[i][j + 0], v1 = acc[i][j + 1];
                float v2 = acc[i][j + 2], v3 = acc[i][j + 3];
                if (EPI == 1) {
                    v0 = softplusf(v0 + bb[j + 0]);
                    v1 = softplusf(v1 + bb[j + 1]);
                    v2 = softplusf(v2 + bb[j + 2]);
                    v3 = softplusf(v3 + bb[j + 3]);
                }
                *(float4*)(C + r * ldc + c) = make_float4(v0, v1, v2, v3);
            }
        }
    }
}

// ---------------------------------------------------------------------------
// Skinny-N SGEMM for x_proj (N=96): BM=32 tiles so 128 blocks cover the grid
// (a 128-row tiler would leave 116 SMs idle). grid = (1, M/32).
// ---------------------------------------------------------------------------
__global__ __launch_bounds__(256) void sgemm_skinny(
    const float* __restrict__ A, const float* __restrict__ B,
    float* __restrict__ C, int M, int N, int K, int lda, int ldb, int ldc)
{
    __shared__ float As[8][32];
    __shared__ float Bs[8][128];

    const int tid  = threadIdx.x;
    const int row0 = blockIdx.y * 32;

    const int arow = tid & 31, ak = tid >> 5;
    const int brow = tid >> 5, bcol = (tid & 31) * 4;
    const int trow = (tid >> 4) * 2, tcol = (tid & 15) * 8;
    const bool bok = bcol < N;

    float acc[2][8];
    #pragma unroll
    for (int i = 0; i < 2; i++)
        #pragma unroll
        for (int j = 0; j < 8; j++) acc[i][j] = 0.0f;

    for (int k0 = 0; k0 < K; k0 += 8) {
        As[ak][arow] = A[(size_t)(row0 + arow) * lda + k0 + ak];
        float4 bv = make_float4(0.f, 0.f, 0.f, 0.f);
        if (bok) bv = *(const float4*)(B + (size_t)(k0 + brow) * ldb + bcol);
        *(float4*)&Bs[brow][bcol] = bv;
        __syncthreads();

        #pragma unroll
        for (int k = 0; k < 8; k++) {
            float a0 = As[k][trow], a1 = As[k][trow + 1];
            float rb[8];
            *(float4*)&rb[0] = *(const float4*)&Bs[k][tcol];
            *(float4*)&rb[4] = *(const float4*)&Bs[k][tcol + 4];
            #pragma unroll
            for (int j = 0; j < 8; j++) {
                acc[0][j] = fmaf(a0, rb[j], acc[0][j]);
                acc[1][j] = fmaf(a1, rb[j], acc[1][j]);
            }
        }
        __syncthreads();
    }

    #pragma unroll
    for (int i = 0; i < 2; i++) {
        size_t r = (size_t)(row0 + trow + i);
        #pragma unroll
        for (int j = 0; j < 8; j += 4) {
            int c = tcol + j;
            if (c < N) {
                *(float4*)(C + r * ldc + c) =
                    make_float4(acc[i][j], acc[i][j+1], acc[i][j+2], acc[i][j+3]);
            }
        }
    }
}

// ---------------------------------------------------------------------------
// Causal depthwise conv1d (k=4, pad left 3) + bias + silu.
// One thread per 4 channels (float4). xi = g_xr[:, 0:2048].
// ---------------------------------------------------------------------------
__global__ __launch_bounds__(256) void conv_silu_kernel(
    const float* __restrict__ xr, const float* __restrict__ cw,
    const float* __restrict__ cb, float* __restrict__ xc)
{
    int i = blockIdx.x * 256 + threadIdx.x;           // < NTOK * DINNER/4
    int d4  = (i & (DINNER / 4 - 1)) << 2;            // channel base (mult of 4)
    int row = i >> 9;                                 // b*L + l
    int l   = row & (LSEQ - 1);

    const float* xp = xr + (size_t)row * (2 * DINNER) + d4;

    float4 xv[DCONV];
    #pragma unroll
    for (int k = 0; k < DCONV; k++) {
        int lk = l - (DCONV - 1) + k;
        if (lk >= 0)
            xv[k] = *(const float4*)(xp + (ptrdiff_t)(k - (DCONV - 1)) * (2 * DINNER));
        else
            xv[k] = make_float4(0.f, 0.f, 0.f, 0.f);
    }
    float4 w0 = *(const float4*)(cw + (size_t)(d4 + 0) * DCONV);
    float4 w1 = *(const float4*)(cw + (size_t)(d4 + 1) * DCONV);
    float4 w2 = *(const float4*)(cw + (size_t)(d4 + 2) * DCONV);
    float4 w3 = *(const float4*)(cw + (size_t)(d4 + 3) * DCONV);
    float4 bv = *(const float4*)(cb + d4);

    float o0 = bv.x + w0.x*xv[0].x + w0.y*xv[1].x + w0.z*xv[2].x + w0.w*xv[3].x;
    float o1 = bv.y + w1.x*xv[0].y + w1.y*xv[1].y + w1.z*xv[2].y + w1.w*xv[3].y;
    float o2 = bv.z + w2.x*xv[0].z + w2.y*xv[1].z + w2.z*xv[2].z + w2.w*xv[3].z;
    float o3 = bv.w + w3.x*xv[0].w + w3.y*xv[1].w + w3.z*xv[2].w + w3.w*xv[3].w;

    *(float4*)(xc + (size_t)row * DINNER + d4) =
        make_float4(siluf(o0), siluf(o1), siluf(o2), siluf(o3));
}

// ---------------------------------------------------------------------------
// Selective scan + output gating.
// 4 threads per (b,d) lane, 4 states each (16384 threads = 128 blocks x 128).
//  - MUFU load: 4 EX2/thread/step instead of 16 (keeps MUFU pipe ~32cyc/step)
//  - PF=8 register-ring software prefetch hides DRAM latency of the streams
//  - y reduced across the 4 state-lanes with shfl.xor (off the recurrence path)
//  - epilogue fuses  y = (scan + u*D) * silu(res)
// ---------------------------------------------------------------------------
#define LOG2E 1.4426950408889634f
#define SCAN_PF 8

__global__ __launch_bounds__(128) void scan_kernel(
    const float* __restrict__ delta, const float* __restrict__ xc,
    const float* __restrict__ xdbl,  const float* __restrict__ xr,
    const float* __restrict__ A_log, const float* __restrict__ Dw,
    float* __restrict__ y)
{
    int t     = blockIdx.x * 128 + threadIdx.x;  // < BSZ*DINNER*4
    int lane4 = t & 3;
    int g     = t >> 2;                          // (b,d) group
    int b     = g >> 11;                         // / DINNER
    int d     = g & (DINNER - 1);
    int n0    = lane4 * 4;

    float A2[4];
    #pragma unroll
    for (int j = 0; j < 4; j++)
        A2[j] = -__expf(A_log[(size_t)d * DSTATE + n0 + j]) * LOG2E;
    float Dd = Dw[d];

    size_t base = ((size_t)b * LSEQ) * DINNER + d;
    const float* dptr   = delta + base;
    const float* uptr   = xc    + base;
    const float* resptr = xr + ((size_t)b * LSEQ) * (2 * DINNER) + DINNER + d;
    const float* bcp    = xdbl + ((size_t)b * LSEQ) * XDBL_W + DTRANK + n0;
    float*       yptr   = y + base;

    float s0 = 0.f, s1 = 0.f, s2 = 0.f, s3 = 0.f;

    float  dbuf[SCAN_PF], ubuf[SCAN_PF], rbuf[SCAN_PF];
    float4 Bbuf[SCAN_PF], Cbuf[SCAN_PF];
    #pragma unroll
    for (int p = 0; p < SCAN_PF; p++) {
        dbuf[p] = dptr[(size_t)p * DINNER];
        ubuf[p] = uptr[(size_t)p * DINNER];
        rbuf[p] = (lane4 == 0) ? resptr[(size_t)p * (2 * DINNER)] : 0.f;
        Bbuf[p] = *(const float4*)(bcp + (size_t)p * XDBL_W);
        Cbuf[p] = *(const float4*)(bcp + (size_t)p * XDBL_W + DSTATE);
    }

    for (int l0 = 0; l0 < LSEQ; l0 += SCAN_PF) {
        #pragma unroll
        for (int p = 0; p < SCAN_PF; p++) {
            int l = l0 + p;
            float  dv = dbuf[p], uv = ubuf[p], rv = rbuf[p];
            float4 Bv = Bbuf[p], Cv = Cbuf[p];

            int ln = l + SCAN_PF;
            if (ln < LSEQ) {
                dbuf[p] = dptr[(size_t)ln * DINNER];
                ubuf[p] = uptr[(size_t)ln * DINNER];
                rbuf[p] = (lane4 == 0) ? resptr[(size_t)ln * (2 * DINNER)] : 0.f;
                Bbuf[p] = *(const float4*)(bcp + (size_t)ln * XDBL_W);
                Cbuf[p] = *(const float4*)(bcp + (size_t)ln * XDBL_W + DSTATE);
            }

            float du = dv * uv;
            float e0 = exp2f(dv * A2[0]);
            float e1 = exp2f(dv * A2[1]);
            float e2 = exp2f(dv * A2[2]);
            float e3 = exp2f(dv * A2[3]);
            s0 = fmaf(e0, s0, du * Bv.x);
            s1 = fmaf(e1, s1, du * Bv.y);
            s2 = fmaf(e2, s2, du * Bv.z);
            s3 = fmaf(e3, s3, du * Bv.w);
            float yv = s0 * Cv.x + s1 * Cv.y + s2 * Cv.z + s3 * Cv.w;

            yv += __shfl_xor_sync(0xffffffffu, yv, 1);
            yv += __shfl_xor_sync(0xffffffffu, yv, 2);

            if (lane4 == 0) {
                float yt = yv + uv * Dd;
                yptr[(size_t)l * DINNER] = yt * siluf(rv);
            }
        }
    }
}

// ---------------------------------------------------------------------------
// Launch: 6 kernels on the capture stream, implicit ordering.
// ---------------------------------------------------------------------------
extern "C" void kernel_launch(void* const* d_in, const int* in_sizes, int n_in,
                              void* d_out, int out_size)
{
    (void)in_sizes; (void)n_in; (void)out_size;
    const float* x          = (const float*)d_in[0];
    const float* in_proj_w  = (const float*)d_in[1];
    const float* conv_w     = (const float*)d_in[2];
    const float* conv_b     = (const float*)d_in[3];
    const float* x_proj_w   = (const float*)d_in[4];
    const float* dt_proj_w  = (const float*)d_in[5];
    const float* dt_proj_b  = (const float*)d_in[6];
    const float* A_log      = (const float*)d_in[7];
    const float* Dw         = (const float*)d_in[8];
    const float* out_proj_w = (const float*)d_in[9];
    float* out = (float*)d_out;

    float *xr, *xc, *xdbl, *delta, *y;
    cudaGetSymbolAddress((void**)&xr,    g_xr);
    cudaGetSymbolAddress((void**)&xc,    g_xc);
    cudaGetSymbolAddress((void**)&xdbl,  g_xdbl);
    cudaGetSymbolAddress((void**)&delta, g_delta);
    cudaGetSymbolAddress((void**)&y,     g_y);

    // 1) xr = x @ in_proj_w          [4096 x 4096, K=1024]
    sgemm128<0><<<dim3((2 * DINNER) / 128, NTOK / 128), 256>>>(
        x, in_proj_w, xr, nullptr,
        NTOK, 2 * DINNER, DMODEL, DMODEL, 2 * DINNER, 2 * DINNER);

    // 2) xc = silu(causal_conv(xi) + b)
    conv_silu_kernel<<<(NTOK * DINNER / 4) / 256, 256>>>(xr, conv_w, conv_b, xc);

    // 3) x_dbl = xc @ x_proj_w       [4096 x 96, K=2048]
    sgemm_skinny<<<dim3(1, NTOK / 32), 256>>>(
        xc, x_proj_w, xdbl, NTOK, XDBL_W, DINNER, DINNER, XDBL_W, XDBL_W);

    // 4) delta = softplus(dt @ dt_proj_w + dt_proj_b)   [4096 x 2048, K=64]
    sgemm128<1><<<dim3(DINNER / 128, NTOK / 128), 256>>>(
        xdbl, dt_proj_w, delta, dt_proj_b,
        NTOK, DINNER, DTRANK, XDBL_W, DINNER, DINNER);

    // 5) y = scan(...) fused with  (+u*D) * silu(res)
    scan_kernel<<<(BSZ * DINNER * 4) / 128, 128>>>(
        delta, xc, xdbl, xr, A_log, Dw, y);

    // 6) out = y @ out_proj_w        [4096 x 1024, K=2048]
    sgemm128<0><<<dim3(DMODEL / 128, NTOK / 128), 256>>>(
        y, out_proj_w, out, nullptr,
        NTOK, DMODEL, DINNER, DINNER, DMODEL, DMODEL);
}

// round 14
// speedup vs baseline: 1.7999x; 1.7999x over previous
#include <cuda_runtime.h>
#include <cuda_bf16.h>
#include <cstdint>
#include <cstddef>

// ---------------------------------------------------------------------------
// Problem constants (MambaBlock): d_model=1024, d_inner=2048, d_conv=4,
// d_state=16, dt_rank=64, B=2, L=2048
// ---------------------------------------------------------------------------
#define BSZ     2
#define LSEQ    2048
#define DMODEL  1024
#define DINNER  2048
#define DCONV   4
#define DSTATE  16
#define DTRANK  64
#define NTOK    (BSZ * LSEQ)          // 4096 tokens
#define XDBL_W  (DTRANK + 2 * DSTATE) // 96

// ---------------------------------------------------------------------------
// Scratch (__device__ globals; no cudaMalloc allowed)
// ---------------------------------------------------------------------------
__device__ float g_xr   [(size_t)NTOK * (2 * DINNER)]; // in_proj out: [xi | res]
__device__ float g_xc   [(size_t)NTOK * DINNER];       // conv+silu out (u)
__device__ float g_xdbl [(size_t)NTOK * XDBL_W];       // [dt(64) | B(16) | C(16)]
__device__ float g_delta[(size_t)NTOK * DINNER];       // softplus(dt @ W + b)
__device__ float g_y    [(size_t)NTOK * DINNER];       // gated scan output

// ---------------------------------------------------------------------------
// Helpers
// ---------------------------------------------------------------------------
__device__ __forceinline__ float softplusf(float x) {
    return fmaxf(x, 0.0f) + log1pf(__expf(-fabsf(x)));
}
__device__ __forceinline__ float siluf(float x) {
    return x * (1.0f / (1.0f + __expf(-x)));
}
__device__ __forceinline__ uint32_t cvt_tf32(float x) {
    uint32_t u;
    asm("cvt.rna.tf32.f32 %0, %1;" : "=r"(u) : "f"(x));
    return u;
}
__device__ __forceinline__ void mma_tf32(float* c, const uint32_t* a, const uint32_t* b) {
    asm volatile(
        "mma.sync.aligned.m16n8k8.row.col.f32.tf32.tf32.f32 "
        "{%0,%1,%2,%3},{%4,%5,%6,%7},{%8,%9},{%0,%1,%2,%3};"
        : "+f"(c[0]), "+f"(c[1]), "+f"(c[2]), "+f"(c[3])
        : "r"(a[0]), "r"(a[1]), "r"(a[2]), "r"(a[3]), "r"(b[0]), "r"(b[1]));
}

// ---------------------------------------------------------------------------
// TF32 tensor-core GEMM via mma.sync (works on base sm_103 target — tcgen05
// is sm_103a-only and this toolchain targets compute_103).
//   C[M,N] = A[M,K] @ W[K,N], all row-major fp32.  M%128==0, N%128==0, K%32==0.
// CTA 128x128, BK=32, 256 threads = 8 warps (2x4), warp tile 64x32.
// Double-buffered cp.async.  Dyn smem = 71680 B.
// Pitches: APITCH=36 (A gather bank = 4g+tq, all 32 banks),
//          BPITCH=136 (B gather bank = 8tq+g, all 32 banks) — both gathers
//          conflict-free; both keep 16B cp.async alignment.
// ---------------------------------------------------------------------------
#define BKK    32
#define APITCH 36
#define BPITCH 136
#define ASTG   (128 * APITCH)            // 4608 floats / stage
#define BSTG   (BKK * BPITCH)            // 4352 floats / stage
#define MMA_SMEM (2 * (ASTG + BSTG) * 4) // 71680 bytes

__global__ __launch_bounds__(256) void gemm_mma(
    const float* __restrict__ A, const float* __restrict__ W,
    float* __restrict__ C, int M, int N, int K)
{
    extern __shared__ float sm[];
    float* Asm = sm;                 // [2][128][APITCH]
    float* Bsm = sm + 2 * ASTG;      // [2][BKK][BPITCH]

    const int tid  = threadIdx.x;
    const int lane = tid & 31, wid = tid >> 5;
    const int wm = wid >> 2, wn = wid & 3;        // warp grid 2x4
    const int g  = lane >> 2, tq = lane & 3;      // mma fragment coords
    const int row0 = blockIdx.y * 128, col0 = blockIdx.x * 128;

    // global->smem load geometry (4 x 16B per thread per operand)
    const int arow = tid >> 3, acol = (tid & 7) * 4;   // A: rows +i*32
    const int bk   = tid >> 5, bcol = (tid & 31) * 4;  // B: k-rows +i*8

    const float* Ag = A + (size_t)(row0 + arow) * K + acol;
    const float* Bg = W + (size_t)bk * N + col0 + bcol;

    auto load = [&](int t) {
        const int s  = t & 1;
        const int k0 = t * BKK;
        float* as = Asm + s * ASTG;
        float* bs = Bsm + s * BSTG;
        #pragma unroll
        for (int i = 0; i < 4; i++) {
            uint32_t d = (uint32_t)__cvta_generic_to_shared(
                as + (arow + i * 32) * APITCH + acol);
            asm volatile("cp.async.cg.shared.global [%0],[%1],16;"
                         :: "r"(d), "l"(Ag + (size_t)i * 32 * K + k0) : "memory");
        }
        #pragma unroll
        for (int i = 0; i < 4; i++) {
            uint32_t d = (uint32_t)__cvta_generic_to_shared(
                bs + (bk + i * 8) * BPITCH + bcol);
            asm volatile("cp.async.cg.shared.global [%0],[%1],16;"
                         :: "r"(d), "l"(Bg + (size_t)(k0 + i * 8) * N) : "memory");
        }
        asm volatile("cp.async.commit_group;" ::: "memory");
    };

    float acc[4][4][4];
    #pragma unroll
    for (int mi = 0; mi < 4; mi++)
        #pragma unroll
        for (int ni = 0; ni < 4; ni++)
            #pragma unroll
            for (int e = 0; e < 4; e++) acc[mi][ni][e] = 0.0f;

    const int nt = K / BKK;
    load(0);
    load(1);

    for (int t = 0; t < nt; t++) {
        asm volatile("cp.async.wait_group 1;" ::: "memory");   // stage t resident
        __syncthreads();
        const float* as = Asm + (t & 1) * ASTG;
        const float* bs = Bsm + (t & 1) * BSTG;

        #pragma unroll
        for (int kk = 0; kk < BKK; kk += 8) {
            uint32_t af[4][4], bf[4][2];
            #pragma unroll
            for (int mi = 0; mi < 4; mi++) {
                const float* p = as + (wm * 64 + mi * 16 + g) * APITCH + kk + tq;
                af[mi][0] = cvt_tf32(p[0]);
                af[mi][1] = cvt_tf32(p[8 * APITCH]);
                af[mi][2] = cvt_tf32(p[4]);
                af[mi][3] = cvt_tf32(p[8 * APITCH + 4]);
            }
            #pragma unroll
            for (int ni = 0; ni < 4; ni++) {
                const float* p = bs + (kk + tq) * BPITCH + wn * 32 + ni * 8 + g;
                bf[ni][0] = cvt_tf32(p[0]);
                bf[ni][1] = cvt_tf32(p[4 * BPITCH]);
            }
            #pragma unroll
            for (int mi = 0; mi < 4; mi++)
                #pragma unroll
                for (int ni = 0; ni < 4; ni++)
                    mma_tf32(acc[mi][ni], af[mi], bf[ni]);
        }
        __syncthreads();
        if (t + 2 < nt) load(t + 2);
    }

    // epilogue: direct float2 stores (c0,c1 / c2,c3 are column-adjacent)
    #pragma unroll
    for (int mi = 0; mi < 4; mi++) {
        int r = row0 + wm * 64 + mi * 16 + g;
        #pragma unroll
        for (int ni = 0; ni < 4; ni++) {
            int c = col0 + wn * 32 + ni * 8 + tq * 2;
            *(float2*)&C[(size_t)r * N + c] =
                make_float2(acc[mi][ni][0], acc[mi][ni][1]);
            *(float2*)&C[(size_t)(r + 8) * N + c] =
                make_float2(acc[mi][ni][2], acc[mi][ni][3]);
        }
    }
}

// ---------------------------------------------------------------------------
// fp32 SGEMM (kept for the small dt_proj GEMM, K=64, fused softplus+bias)
// ---------------------------------------------------------------------------
template <int EPI>
__global__ __launch_bounds__(256) void sgemm128(
    const float* __restrict__ A, const float* __restrict__ B,
    float* __restrict__ C, const float* __restrict__ bias,
    int M, int N, int K, int lda, int ldb, int ldc)
{
    __shared__ float As[8][128];
    __shared__ float Bs[8][128];

    const int tid  = threadIdx.x;
    const int row0 = blockIdx.y * 128;
    const int col0 = blockIdx.x * 128;

    const int arow = tid >> 1;
    const int acol = (tid & 1) * 4;
    const int brow = tid >> 5;
    const int bcol = (tid & 31) * 4;
    const int trow = (tid >> 4) * 8;
    const int tcol = (tid & 15) * 8;

    float acc[8][8];
    #pragma unroll
    for (int i = 0; i < 8; i++)
        #pragma unroll
        for (int j = 0; j < 8; j++) acc[i][j] = 0.0f;

    const float* Ap = A + (size_t)(row0 + arow) * lda + acol;
    const float* Bp = B + (size_t)brow * ldb + col0 + bcol;
    const bool bok = (col0 + bcol) < N;

    for (int k0 = 0; k0 < K; k0 += 8) {
        float4 av = *(const float4*)(Ap + k0);
        As[acol + 0][arow] = av.x;
        As[acol + 1][arow] = av.y;
        As[acol + 2][arow] = av.z;
        As[acol + 3][arow] = av.w;
        float4 bv = make_float4(0.f, 0.f, 0.f, 0.f);
        if (bok) bv = *(const float4*)(Bp + (size_t)k0 * ldb);
        *(float4*)&Bs[brow][bcol] = bv;
        __syncthreads();

        #pragma unroll
        for (int k = 0; k < 8; k++) {
            float ra[8], rb[8];
            *(float4*)&ra[0] = *(const float4*)&As[k][trow];
            *(float4*)&ra[4] = *(const float4*)&As[k][trow + 4];
            *(float4*)&rb[0] = *(const float4*)&Bs[k][tcol];
            *(float4*)&rb[4] = *(const float4*)&Bs[k][tcol + 4];
            #pragma unroll
            for (int i = 0; i < 8; i++)
                #pragma unroll
                for (int j = 0; j < 8; j++)
                    acc[i][j] = fmaf(ra[i], rb[j], acc[i][j]);
        }
        __syncthreads();
    }

    float bb[8];
    if (EPI == 1) {
        #pragma unroll
        for (int j = 0; j < 8; j++) bb[j] = bias[col0 + tcol + j];
    }

    #pragma unroll
    for (int i = 0; i < 8; i++) {
        size_t r = (size_t)(row0 + trow + i);
        #pragma unroll
        for (int j = 0; j < 8; j += 4) {
            int c = col0 + tcol + j;
            if (c < N) {
                float v0 = acc[i][j + 0], v1 = acc[i][j + 1];
                float v2 = acc[i][j + 2], v3 = acc[i][j + 3];
                if (EPI == 1) {
                    v0 = softplusf(v0 + bb[j + 0]);
                    v1 = softplusf(v1 + bb[j + 1]);
                    v2 = softplusf(v2 + bb[j + 2]);
                    v3 = softplusf(v3 + bb[j + 3]);
                }
                *(float4*)(C + r * ldc + c) = make_float4(v0, v1, v2, v3);
            }
        }
    }
}

// ---------------------------------------------------------------------------
// Skinny-N SGEMM for x_proj (N=96): BM=32 tiles -> 128 blocks fill the chip.
// ---------------------------------------------------------------------------
__global__ __launch_bounds__(256) void sgemm_skinny(
    const float* __restrict__ A, const float* __restrict__ B,
    float* __restrict__ C, int M, int N, int K, int lda, int ldb, int ldc)
{
    __shared__ float As[8][32];
    __shared__ float Bs[8][128];

    const int tid  = threadIdx.x;
    const int row0 = blockIdx.y * 32;

    const int arow = tid & 31, ak = tid >> 5;
    const int brow = tid >> 5, bcol = (tid & 31) * 4;
    const int trow = (tid >> 4) * 2, tcol = (tid & 15) * 8;
    const bool bok = bcol < N;

    float acc[2][8];
    #pragma unroll
    for (int i = 0; i < 2; i++)
        #pragma unroll
        for (int j = 0; j < 8; j++) acc[i][j] = 0.0f;

    for (int k0 = 0; k0 < K; k0 += 8) {
        As[ak][arow] = A[(size_t)(row0 + arow) * lda + k0 + ak];
        float4 bv = make_float4(0.f, 0.f, 0.f, 0.f);
        if (bok) bv = *(const float4*)(B + (size_t)(k0 + brow) * ldb + bcol);
        *(float4*)&Bs[brow][bcol] = bv;
        __syncthreads();

        #pragma unroll
        for (int k = 0; k < 8; k++) {
            float a0 = As[k][trow], a1 = As[k][trow + 1];
            float rb[8];
            *(float4*)&rb[0] = *(const float4*)&Bs[k][tcol];
            *(float4*)&rb[4] = *(const float4*)&Bs[k][tcol + 4];
            #pragma unroll
            for (int j = 0; j < 8; j++) {
                acc[0][j] = fmaf(a0, rb[j], acc[0][j]);
                acc[1][j] = fmaf(a1, rb[j], acc[1][j]);
            }
        }
        __syncthreads();
    }

    #pragma unroll
    for (int i = 0; i < 2; i++) {
        size_t r = (size_t)(row0 + trow + i);
        #pragma unroll
        for (int j = 0; j < 8; j += 4) {
            int c = tcol + j;
            if (c < N) {
                *(float4*)(C + r * ldc + c) =
                    make_float4(acc[i][j], acc[i][j+1], acc[i][j+2], acc[i][j+3]);
            }
        }
    }
}

// ---------------------------------------------------------------------------
// Causal depthwise conv1d (k=4) + bias + silu. One thread per 4 channels.
// ---------------------------------------------------------------------------
__global__ __launch_bounds__(256) void conv_silu_kernel(
    const float* __restrict__ xr, const float* __restrict__ cw,
    const float* __restrict__ cb, float* __restrict__ xc)
{
    int i = blockIdx.x * 256 + threadIdx.x;
    int d4  = (i & (DINNER / 4 - 1)) << 2;
    int row = i >> 9;
    int l   = row & (LSEQ - 1);

    const float* xp = xr + (size_t)row * (2 * DINNER) + d4;

    float4 xv[DCONV];
    #pragma unroll
    for (int k = 0; k < DCONV; k++) {
        int lk = l - (DCONV - 1) + k;
        if (lk >= 0)
            xv[k] = *(const float4*)(xp + (ptrdiff_t)(k - (DCONV - 1)) * (2 * DINNER));
        else
            xv[k] = make_float4(0.f, 0.f, 0.f, 0.f);
    }
    float4 w0 = *(const float4*)(cw + (size_t)(d4 + 0) * DCONV);
    float4 w1 = *(const float4*)(cw + (size_t)(d4 + 1) * DCONV);
    float4 w2 = *(const float4*)(cw + (size_t)(d4 + 2) * DCONV);
    float4 w3 = *(const float4*)(cw + (size_t)(d4 + 3) * DCONV);
    float4 bv = *(const float4*)(cb + d4);

    float o0 = bv.x + w0.x*xv[0].x + w0.y*xv[1].x + w0.z*xv[2].x + w0.w*xv[3].x;
    float o1 = bv.y + w1.x*xv[0].y + w1.y*xv[1].y + w1.z*xv[2].y + w1.w*xv[3].y;
    float o2 = bv.z + w2.x*xv[0].z + w2.y*xv[1].z + w2.z*xv[2].z + w2.w*xv[3].z;
    float o3 = bv.w + w3.x*xv[0].w + w3.y*xv[1].w + w3.z*xv[2].w + w3.w*xv[3].w;

    *(float4*)(xc + (size_t)row * DINNER + d4) =
        make_float4(siluf(o0), siluf(o1), siluf(o2), siluf(o3));
}

// ---------------------------------------------------------------------------
// Selective scan + output gating (4 threads x 4 states per (b,d) lane,
// PF=8 register-ring prefetch, shfl reduction, fused (+u*D)*silu(res)).
// ---------------------------------------------------------------------------
#define LOG2E 1.4426950408889634f
#define SCAN_PF 8

__global__ __launch_bounds__(128) void scan_kernel(
    const float* __restrict__ delta, const float* __restrict__ xc,
    const float* __restrict__ xdbl,  const float* __restrict__ xr,
    const float* __restrict__ A_log, const float* __restrict__ Dw,
    float* __restrict__ y)
{
    int t     = blockIdx.x * 128 + threadIdx.x;
    int lane4 = t & 3;
    int g     = t >> 2;
    int b     = g >> 11;
    int d     = g & (DINNER - 1);
    int n0    = lane4 * 4;

    float A2[4];
    #pragma unroll
    for (int j = 0; j < 4; j++)
        A2[j] = -__expf(A_log[(size_t)d * DSTATE + n0 + j]) * LOG2E;
    float Dd = Dw[d];

    size_t base = ((size_t)b * LSEQ) * DINNER + d;
    const float* dptr   = delta + base;
    const float* uptr   = xc    + base;
    const float* resptr = xr + ((size_t)b * LSEQ) * (2 * DINNER) + DINNER + d;
    const float* bcp    = xdbl + ((size_t)b * LSEQ) * XDBL_W + DTRANK + n0;
    float*       yptr   = y + base;

    float s0 = 0.f, s1 = 0.f, s2 = 0.f, s3 = 0.f;

    float  dbuf[SCAN_PF], ubuf[SCAN_PF], rbuf[SCAN_PF];
    float4 Bbuf[SCAN_PF], Cbuf[SCAN_PF];
    #pragma unroll
    for (int p = 0; p < SCAN_PF; p++) {
        dbuf[p] = dptr[(size_t)p * DINNER];
        ubuf[p] = uptr[(size_t)p * DINNER];
        rbuf[p] = (lane4 == 0) ? resptr[(size_t)p * (2 * DINNER)] : 0.f;
        Bbuf[p] = *(const float4*)(bcp + (size_t)p * XDBL_W);
        Cbuf[p] = *(const float4*)(bcp + (size_t)p * XDBL_W + DSTATE);
    }

    for (int l0 = 0; l0 < LSEQ; l0 += SCAN_PF) {
        #pragma unroll
        for (int p = 0; p < SCAN_PF; p++) {
            int l = l0 + p;
            float  dv = dbuf[p], uv = ubuf[p], rv = rbuf[p];
            float4 Bv = Bbuf[p], Cv = Cbuf[p];

            int ln = l + SCAN_PF;
            if (ln < LSEQ) {
                dbuf[p] = dptr[(size_t)ln * DINNER];
                ubuf[p] = uptr[(size_t)ln * DINNER];
                rbuf[p] = (lane4 == 0) ? resptr[(size_t)ln * (2 * DINNER)] : 0.f;
                Bbuf[p] = *(const float4*)(bcp + (size_t)ln * XDBL_W);
                Cbuf[p] = *(const float4*)(bcp + (size_t)ln * XDBL_W + DSTATE);
            }

            float du = dv * uv;
            float e0 = exp2f(dv * A2[0]);
            float e1 = exp2f(dv * A2[1]);
            float e2 = exp2f(dv * A2[2]);
            float e3 = exp2f(dv * A2[3]);
            s0 = fmaf(e0, s0, du * Bv.x);
            s1 = fmaf(e1, s1, du * Bv.y);
            s2 = fmaf(e2, s2, du * Bv.z);
            s3 = fmaf(e3, s3, du * Bv.w);
            float yv = s0 * Cv.x + s1 * Cv.y + s2 * Cv.z + s3 * Cv.w;

            yv += __shfl_xor_sync(0xffffffffu, yv, 1);
            yv += __shfl_xor_sync(0xffffffffu, yv, 2);

            if (lane4 == 0) {
                float yt = yv + uv * Dd;
                yptr[(size_t)l * DINNER] = yt * siluf(rv);
            }
        }
    }
}

// ---------------------------------------------------------------------------
// Launch
// ---------------------------------------------------------------------------
extern "C" void kernel_launch(void* const* d_in, const int* in_sizes, int n_in,
                              void* d_out, int out_size)
{
    (void)in_sizes; (void)n_in; (void)out_size;
    const float* x          = (const float*)d_in[0];
    const float* in_proj_w  = (const float*)d_in[1];
    const float* conv_w     = (const float*)d_in[2];
    const float* conv_b     = (const float*)d_in[3];
    const float* x_proj_w   = (const float*)d_in[4];
    const float* dt_proj_w  = (const float*)d_in[5];
    const float* dt_proj_b  = (const float*)d_in[6];
    const float* A_log      = (const float*)d_in[7];
    const float* Dw         = (const float*)d_in[8];
    const float* out_proj_w = (const float*)d_in[9];
    float* out = (float*)d_out;

    float *xr, *xc, *xdbl, *delta, *y;
    cudaGetSymbolAddress((void**)&xr,    g_xr);
    cudaGetSymbolAddress((void**)&xc,    g_xc);
    cudaGetSymbolAddress((void**)&xdbl,  g_xdbl);
    cudaGetSymbolAddress((void**)&delta, g_delta);
    cudaGetSymbolAddress((void**)&y,     g_y);

    // idempotent (no static guards allowed)
    cudaFuncSetAttribute(gemm_mma, cudaFuncAttributeMaxDynamicSharedMemorySize, MMA_SMEM);

    // 1) xr = x @ in_proj_w   (tf32 mma.sync)  [4096 x 4096, K=1024]
    gemm_mma<<<dim3((2 * DINNER) / 128, NTOK / 128), 256, MMA_SMEM>>>(
        x, in_proj_w, xr, NTOK, 2 * DINNER, DMODEL);

    // 2) xc = silu(causal_conv(xi) + b)
    conv_silu_kernel<<<(NTOK * DINNER / 4) / 256, 256>>>(xr, conv_w, conv_b, xc);

    // 3) x_dbl = xc @ x_proj_w   (fp32, keeps scan inputs accurate)
    sgemm_skinny<<<dim3(1, NTOK / 32), 256>>>(
        xc, x_proj_w, xdbl, NTOK, XDBL_W, DINNER, DINNER, XDBL_W, XDBL_W);

    // 4) delta = softplus(dt @ dt_proj_w + b)   (fp32)
    sgemm128<1><<<dim3(DINNER / 128, NTOK / 128), 256>>>(
        xdbl, dt_proj_w, delta, dt_proj_b,
        NTOK, DINNER, DTRANK, XDBL_W, DINNER, DINNER);

    // 5) y = scan + gating
    scan_kernel<<<(BSZ * DINNER * 4) / 128, 128>>>(
        delta, xc, xdbl, xr, A_log, Dw, y);

    // 6) out = y @ out_proj_w   (tf32 mma.sync)  [4096 x 1024, K=2048]
    gemm_mma<<<dim3(DMODEL / 128, NTOK / 128), 256, MMA_SMEM>>>(
        y, out_proj_w, out, NTOK, DMODEL, DINNER);
}